// round 3
// baseline (speedup 1.0000x reference)
#include <cuda_runtime.h>
#include <cstdint>

// ============================================================================
// X[16,4096,256] -> proj(256->128) +bp -> relu(W1 +b1) -> W2 +b2 = Y
// out[b,n,:] = sum_m Y[b,m,:] - Y[b,n,:]
// Tensor path: mma.sync.m16n8k8 tf32 (sm_103-portable; tcgen05 rejected by
// the harness's compute_103 PTX target).
// ============================================================================

__device__ __align__(16) float g_wpack[8 * 8192];   // 8 chunks x 32KB packed tf32 weights
__device__ float g_part[16 * 8 * 128];

// ---------------- helpers ----------------
__device__ __forceinline__ uint32_t smem_u32(const void* p) {
    uint32_t a;
    asm("{ .reg .u64 t; cvta.to.shared.u64 t, %1; cvt.u32.u64 %0, t; }" : "=r"(a) : "l"(p));
    return a;
}
__device__ __forceinline__ float lds32f(uint32_t a) {
    float v; asm volatile("ld.shared.f32 %0, [%1];" : "=f"(v) : "r"(a)); return v;
}
__device__ __forceinline__ void lds64f(uint32_t a, float& x, float& y) {
    asm volatile("ld.shared.v2.f32 {%0,%1}, [%2];" : "=f"(x), "=f"(y) : "r"(a));
}
__device__ __forceinline__ void lds128u(uint32_t a, uint32_t& x, uint32_t& y, uint32_t& z, uint32_t& w) {
    asm volatile("ld.shared.v4.b32 {%0,%1,%2,%3}, [%4];" : "=r"(x), "=r"(y), "=r"(z), "=r"(w) : "r"(a));
}
__device__ __forceinline__ void sts64f(uint32_t a, float x, float y) {
    asm volatile("st.shared.v2.f32 [%0], {%1,%2};" :: "r"(a), "f"(x), "f"(y));
}
__device__ __forceinline__ uint32_t cvt_tf32(float f) {
    uint32_t u; asm("cvt.rna.tf32.f32 %0, %1;" : "=r"(u) : "f"(f)); return u;
}
__device__ __forceinline__ void mma8(float* d,
                                     uint32_t a0, uint32_t a1, uint32_t a2, uint32_t a3,
                                     uint32_t b0, uint32_t b1) {
    asm volatile(
        "mma.sync.aligned.m16n8k8.row.col.f32.tf32.tf32.f32 "
        "{%0,%1,%2,%3}, {%4,%5,%6,%7}, {%8,%9}, {%0,%1,%2,%3};"
        : "+f"(d[0]), "+f"(d[1]), "+f"(d[2]), "+f"(d[3])
        : "r"(a0), "r"(a1), "r"(a2), "r"(a3), "r"(b0), "r"(b1));
}
#define CP16(dst, src)  asm volatile("cp.async.cg.shared.global [%0], [%1], 16;" :: "r"(dst), "l"(src))
#define CP_COMMIT()     asm volatile("cp.async.commit_group;" ::: "memory")
#define CP_WAIT(n)      asm volatile("cp.async.wait_group %0;" :: "n"(n) : "memory")

// ============================================================================
// prep: pack weights (tf32-rounded) into lane-ordered quad layout.
// chunk c (0..7) = 32KB covering K-slice of 64 rows x 128 cols:
//   chunks 0-3: Wp rows c*64..; 4-5: W1; 6-7: W2.
// float index within chunk: ((ks*8+bp)*32 + lane)*4 + q, where
//   k_local = ks*8 + (lane%4) + (q%2)*4 ;  n = bp*16 + (lane/4) + (q/2)*8
// so one LDS.128 per (ks,bp) yields B-frags (b0,b1) for n-blocks 2bp, 2bp+1.
// ============================================================================
__global__ void prep_kernel(const float* __restrict__ Wp,
                            const float* __restrict__ W1,
                            const float* __restrict__ W2) {
    int i = blockIdx.x * 256 + threadIdx.x;          // 65536 total
    int chunk = i >> 13;
    int within = i & 8191;
    int q = within & 3, ln = (within >> 2) & 31, bpks = within >> 7;
    int bpi = bpks & 7, ks = bpks >> 3;
    int kl = ks * 8 + (ln & 3) + (q & 1) * 4;
    int n = bpi * 16 + (ln >> 2) + (q >> 1) * 8;
    const float* W;
    int krow;
    if (chunk < 4)      { W = Wp; krow = chunk * 64 + kl; }
    else if (chunk < 6) { W = W1; krow = (chunk - 4) * 64 + kl; }
    else                { W = W2; krow = (chunk - 6) * 64 + kl; }
    uint32_t v = cvt_tf32(W[(size_t)krow * 128 + n]);
    g_wpack[i] = __uint_as_float(v);
}

// ============================================================================
// fused kernel: 512 CTAs x 128 threads (4 warps, each warp m=32 rows)
// ============================================================================
#define A_STR 132                     // floats per A row (128 + 4 pad)
#define SM_A0   0
#define SM_A1   67584                 // 128*132*4
#define SM_B0   135168
#define SM_B1   167936
#define SM_BIAS 200704                // bp[128], b1[128], b2[128]
#define SMEM_SZ 202240

__global__ void __launch_bounds__(128, 1) fused_kernel(
    const float* __restrict__ X,
    const float* __restrict__ bp,
    const float* __restrict__ b1,
    const float* __restrict__ b2,
    float* __restrict__ out)
{
    extern __shared__ char smem[];
    const uint32_t sb = smem_u32(smem);
    const int tid = threadIdx.x;
    const int l = tid & 31;
    const int w = tid >> 5;
    const int wrow = w * 32;
    const int t = blockIdx.x;

    // biases -> smem
    ((float*)(smem + SM_BIAS))[tid]       = bp[tid];
    ((float*)(smem + SM_BIAS))[128 + tid] = b1[tid];
    ((float*)(smem + SM_BIAS))[256 + tid] = b2[tid];

    // prologue: group0 = Xh0->A0 + W0->B0 ; group1 = Xh1->A1 + W1->B1
    const float* xbase = X + (size_t)t * 128 * 256;
    #pragma unroll
    for (int h = 0; h < 2; ++h) {
        uint32_t adst = sb + (h ? SM_A1 : SM_A0);
        for (int i = tid; i < 4096; i += 128) {
            int r = i >> 5, c16 = i & 31;
            CP16(adst + r * 528 + c16 * 16,
                 xbase + (size_t)r * 256 + h * 128 + c16 * 4);
        }
        uint32_t bdst = sb + (h ? SM_B1 : SM_B0);
        const float* wsrc = g_wpack + h * 8192;
        for (int i = tid; i < 2048; i += 128) CP16(bdst + i * 16, wsrc + i * 4);
        CP_COMMIT();
    }

    float acc[2][16][4];
    #pragma unroll
    for (int m = 0; m < 2; ++m)
        #pragma unroll
        for (int nb = 0; nb < 16; ++nb)
            #pragma unroll
            for (int k = 0; k < 4; ++k) acc[m][nb][k] = 0.f;

    for (int ch = 0; ch < 8; ++ch) {
        if (ch < 7) { CP_WAIT(1); } else { CP_WAIT(0); }
        __syncthreads();

        // chunks 0,1 read A0 (Xh0); 2,3 A1 (Xh1); 4,5 A0 (H1); 6,7 A1 (H2)
        const uint32_t abase = sb + (((ch >> 1) & 1) ? SM_A1 : SM_A0) + (ch & 1) * 256;
        const uint32_t bbase = sb + ((ch & 1) ? SM_B1 : SM_B0);

        #pragma unroll
        for (int ks = 0; ks < 8; ++ks) {
            uint32_t ab = abase + (uint32_t)(wrow + (l >> 2)) * 528 + (uint32_t)(ks * 8 + (l & 3)) * 4;
            uint32_t A[2][4];
            #pragma unroll
            for (int mb = 0; mb < 2; ++mb) {
                uint32_t p = ab + mb * (16 * 528);
                A[mb][0] = cvt_tf32(lds32f(p));
                A[mb][1] = cvt_tf32(lds32f(p + 8 * 528));
                A[mb][2] = cvt_tf32(lds32f(p + 16));
                A[mb][3] = cvt_tf32(lds32f(p + 8 * 528 + 16));
            }
            #pragma unroll
            for (int bpi = 0; bpi < 8; ++bpi) {
                uint32_t q0, q1, q2, q3;
                lds128u(bbase + (uint32_t)(ks * 8 + bpi) * 512 + (uint32_t)l * 16, q0, q1, q2, q3);
                mma8(acc[0][2 * bpi],     A[0][0], A[0][1], A[0][2], A[0][3], q0, q1);
                mma8(acc[1][2 * bpi],     A[1][0], A[1][1], A[1][2], A[1][3], q0, q1);
                mma8(acc[0][2 * bpi + 1], A[0][0], A[0][1], A[0][2], A[0][3], q2, q3);
                mma8(acc[1][2 * bpi + 1], A[1][0], A[1][1], A[1][2], A[1][3], q2, q3);
            }
        }

        if (ch == 3 || ch == 5) {
            // epilogue -> smem (H1 to A0 after ch3, H2 to A1 after ch5)
            const uint32_t dst = sb + (ch == 3 ? SM_A0 : SM_A1);
            const uint32_t bo  = sb + SM_BIAS + (ch == 3 ? 0 : 512);
            const bool dorelu = (ch == 5);
            #pragma unroll
            for (int nb = 0; nb < 16; ++nb) {
                float bx, by;
                lds64f(bo + (uint32_t)(nb * 8 + (l & 3) * 2) * 4, bx, by);
                #pragma unroll
                for (int mb = 0; mb < 2; ++mb) {
                    float v0 = acc[mb][nb][0] + bx, v1 = acc[mb][nb][1] + by;
                    float v2 = acc[mb][nb][2] + bx, v3 = acc[mb][nb][3] + by;
                    if (dorelu) {
                        v0 = fmaxf(v0, 0.f); v1 = fmaxf(v1, 0.f);
                        v2 = fmaxf(v2, 0.f); v3 = fmaxf(v3, 0.f);
                    }
                    uint32_t sa = dst + (uint32_t)(wrow + mb * 16 + (l >> 2)) * 528
                                      + (uint32_t)(nb * 8 + (l & 3) * 2) * 4;
                    sts64f(sa, v0, v1);
                    sts64f(sa + 8 * 528, v2, v3);
                    acc[mb][nb][0] = 0.f; acc[mb][nb][1] = 0.f;
                    acc[mb][nb][2] = 0.f; acc[mb][nb][3] = 0.f;
                }
            }
        } else if (ch == 7) {
            // final epilogue -> global Y
            const size_t rb = (size_t)t * 128 + wrow + (l >> 2);
            #pragma unroll
            for (int nb = 0; nb < 16; ++nb) {
                float bx, by;
                lds64f(sb + SM_BIAS + 1024 + (uint32_t)(nb * 8 + (l & 3) * 2) * 4, bx, by);
                #pragma unroll
                for (int mb = 0; mb < 2; ++mb) {
                    float v0 = acc[mb][nb][0] + bx, v1 = acc[mb][nb][1] + by;
                    float v2 = acc[mb][nb][2] + bx, v3 = acc[mb][nb][3] + by;
                    size_t r0 = (rb + mb * 16) * 128 + nb * 8 + (l & 3) * 2;
                    *(float2*)(out + r0)            = make_float2(v0, v1);
                    *(float2*)(out + r0 + 8 * 128)  = make_float2(v2, v3);
                }
            }
        }

        __syncthreads();

        if (ch + 2 < 8) {   // prefetch weight chunk ch+2 into buffer (ch&1)
            uint32_t bdst = sb + ((ch & 1) ? SM_B1 : SM_B0);
            const float* wsrc = g_wpack + (ch + 2) * 8192;
            for (int i = tid; i < 2048; i += 128) CP16(bdst + i * 16, wsrc + i * 4);
            CP_COMMIT();
        }
    }
}

// ---------------- reduction: partial column sums ----------------
__global__ void colsum_part(const float* __restrict__ Y) {
    int b = blockIdx.x, c = blockIdx.y, d = threadIdx.x;
    const float* p = Y + ((size_t)b * 4096 + (size_t)c * 512) * 128 + d;
    float s = 0.f;
    #pragma unroll 8
    for (int n = 0; n < 512; ++n) s += p[(size_t)n * 128];
    g_part[(b * 8 + c) * 128 + d] = s;
}

// ---------------- out = S - Y (in place) ----------------
__global__ void subtract_kernel(float* __restrict__ out) {
    __shared__ float S[128];
    int b = blockIdx.x, nc = blockIdx.y, t = threadIdx.x;
    if (t < 128) {
        float s = 0.f;
        #pragma unroll
        for (int c = 0; c < 8; ++c) s += g_part[(b * 8 + c) * 128 + t];
        S[t] = s;
    }
    __syncthreads();
    float* p = out + ((size_t)b * 4096 + (size_t)nc * 128) * 128;
    for (int i = t; i < 128 * 128; i += 256)
        p[i] = S[i & 127] - p[i];
}

// ---------------- launch ----------------
extern "C" void kernel_launch(void* const* d_in, const int* in_sizes, int n_in,
                              void* d_out, int out_size) {
    const float* X  = (const float*)d_in[0];
    const float* Wp = (const float*)d_in[1];
    const float* bp = (const float*)d_in[2];
    const float* W1 = (const float*)d_in[3];
    const float* b1 = (const float*)d_in[4];
    const float* W2 = (const float*)d_in[5];
    const float* b2 = (const float*)d_in[6];
    float* out = (float*)d_out;

    cudaFuncSetAttribute(fused_kernel,
                         cudaFuncAttributeMaxDynamicSharedMemorySize, SMEM_SZ);

    prep_kernel<<<256, 256>>>(Wp, W1, W2);
    fused_kernel<<<512, 128, SMEM_SZ>>>(X, bp, b1, b2, out);
    colsum_part<<<dim3(16, 8), 128>>>(out);
    subtract_kernel<<<dim3(16, 32), 256>>>(out);
}

// round 4
// speedup vs baseline: 1.2931x; 1.2931x over previous
#include <cuda_runtime.h>
#include <cstdint>

// ============================================================================
// X[16,4096,256] -> proj(256->128)+bp -> relu(W1+b1) -> W2+b2 = Y
// out[b,n,:] = sum_m Y[b,m,:] - Y[b,n,:]
// mma.sync.m16n8k8 tf32 (compute_103-portable). 512 CTAs x 256 thr (8 warps),
// warp (w): rows (w>>1)*32..+32, n-half (w&1)*64..+64.
// Column sums fused into the final epilogue -> g_part[tile][128].
// ============================================================================

__device__ __align__(16) float g_wpack[8 * 8192];   // 8 chunks x 32KB packed tf32 weights
__device__ float g_part[512 * 128];

// ---------------- helpers ----------------
__device__ __forceinline__ uint32_t smem_u32(const void* p) {
    uint32_t a;
    asm("{ .reg .u64 t; cvta.to.shared.u64 t, %1; cvt.u32.u64 %0, t; }" : "=r"(a) : "l"(p));
    return a;
}
__device__ __forceinline__ float lds32f(uint32_t a) {
    float v; asm volatile("ld.shared.f32 %0, [%1];" : "=f"(v) : "r"(a)); return v;
}
__device__ __forceinline__ void lds64f(uint32_t a, float& x, float& y) {
    asm volatile("ld.shared.v2.f32 {%0,%1}, [%2];" : "=f"(x), "=f"(y) : "r"(a));
}
__device__ __forceinline__ void lds128u(uint32_t a, uint32_t& x, uint32_t& y, uint32_t& z, uint32_t& w) {
    asm volatile("ld.shared.v4.b32 {%0,%1,%2,%3}, [%4];" : "=r"(x), "=r"(y), "=r"(z), "=r"(w) : "r"(a));
}
__device__ __forceinline__ void sts64f(uint32_t a, float x, float y) {
    asm volatile("st.shared.v2.f32 [%0], {%1,%2};" :: "r"(a), "f"(x), "f"(y));
}
__device__ __forceinline__ uint32_t cvt_tf32(float f) {
    uint32_t u; asm("cvt.rna.tf32.f32 %0, %1;" : "=r"(u) : "f"(f)); return u;
}
__device__ __forceinline__ void mma8(float* d,
                                     uint32_t a0, uint32_t a1, uint32_t a2, uint32_t a3,
                                     uint32_t b0, uint32_t b1) {
    asm volatile(
        "mma.sync.aligned.m16n8k8.row.col.f32.tf32.tf32.f32 "
        "{%0,%1,%2,%3}, {%4,%5,%6,%7}, {%8,%9}, {%0,%1,%2,%3};"
        : "+f"(d[0]), "+f"(d[1]), "+f"(d[2]), "+f"(d[3])
        : "r"(a0), "r"(a1), "r"(a2), "r"(a3), "r"(b0), "r"(b1));
}
#define CP16(dst, src)  asm volatile("cp.async.cg.shared.global [%0], [%1], 16;" :: "r"(dst), "l"(src))
#define CP_COMMIT()     asm volatile("cp.async.commit_group;" ::: "memory")
#define CP_WAIT(n)      asm volatile("cp.async.wait_group %0;" :: "n"(n) : "memory")

// ============================================================================
// prep: pack weights (tf32-rounded) into lane-ordered quad layout.
// chunk c (0..7) = 32KB K-slice of 64 rows x 128 cols (0-3:Wp, 4-5:W1, 6-7:W2).
// float idx within chunk: ((ks*8+bp)*32 + lane)*4 + q, with
//   k_local = ks*8 + (lane%4) + (q%2)*4 ;  n = bp*16 + (lane/4) + (q/2)*8
// ============================================================================
__global__ void prep_kernel(const float* __restrict__ Wp,
                            const float* __restrict__ W1,
                            const float* __restrict__ W2) {
    int i = blockIdx.x * 256 + threadIdx.x;          // 65536 total
    int chunk = i >> 13;
    int within = i & 8191;
    int q = within & 3, ln = (within >> 2) & 31, bpks = within >> 7;
    int bpi = bpks & 7, ks = bpks >> 3;
    int kl = ks * 8 + (ln & 3) + (q & 1) * 4;
    int n = bpi * 16 + (ln >> 2) + (q >> 1) * 8;
    const float* W;
    int krow;
    if (chunk < 4)      { W = Wp; krow = chunk * 64 + kl; }
    else if (chunk < 6) { W = W1; krow = (chunk - 4) * 64 + kl; }
    else                { W = W2; krow = (chunk - 6) * 64 + kl; }
    uint32_t v = cvt_tf32(W[(size_t)krow * 128 + n]);
    g_wpack[i] = __uint_as_float(v);
}

// ============================================================================
// fused kernel
// ============================================================================
#define SM_A0   0
#define SM_A1   67584                 // 128*132*4
#define SM_B0   135168
#define SM_B1   167936
#define SM_BIAS 200704                // bp[128], b1[128], b2[128]
#define SM_RED  202240                // 4*128 floats
#define SMEM_SZ 204288

__global__ void __launch_bounds__(256, 1) fused_kernel(
    const float* __restrict__ X,
    const float* __restrict__ bp,
    const float* __restrict__ b1,
    const float* __restrict__ b2,
    float* __restrict__ out)
{
    extern __shared__ char smem[];
    const uint32_t sb = smem_u32(smem);
    const int tid = threadIdx.x;
    const int l = tid & 31;
    const int w = tid >> 5;
    const int wrow = (w >> 1) * 32;        // row group
    const int nh = w & 1;                  // n-half (0: cols 0-63, 1: 64-127)
    const int t = blockIdx.x;

    if (tid < 128) {
        ((float*)(smem + SM_BIAS))[tid]       = bp[tid];
        ((float*)(smem + SM_BIAS))[128 + tid] = b1[tid];
        ((float*)(smem + SM_BIAS))[256 + tid] = b2[tid];
    }

    // prologue: group0 = Xh0->A0 + W0->B0 ; group1 = Xh1->A1 + W1->B1
    const float* xbase = X + (size_t)t * 128 * 256;
    #pragma unroll
    for (int h = 0; h < 2; ++h) {
        uint32_t adst = sb + (h ? SM_A1 : SM_A0);
        for (int i = tid; i < 4096; i += 256) {
            int r = i >> 5, c16 = i & 31;
            CP16(adst + r * 528 + c16 * 16,
                 xbase + (size_t)r * 256 + h * 128 + c16 * 4);
        }
        uint32_t bdst = sb + (h ? SM_B1 : SM_B0);
        const float* wsrc = g_wpack + h * 8192;
        for (int i = tid; i < 2048; i += 256) CP16(bdst + i * 16, wsrc + i * 4);
        CP_COMMIT();
    }

    float acc[2][8][4];
    #pragma unroll
    for (int m = 0; m < 2; ++m)
        #pragma unroll
        for (int nb = 0; nb < 8; ++nb)
            #pragma unroll
            for (int k = 0; k < 4; ++k) acc[m][nb][k] = 0.f;

    for (int ch = 0; ch < 8; ++ch) {
        if (ch < 7) { CP_WAIT(1); } else { CP_WAIT(0); }
        __syncthreads();

        // chunks 0,1 read A0 (Xh0); 2,3 A1 (Xh1); 4,5 A0 (H1); 6,7 A1 (H2)
        const uint32_t abase = sb + (((ch >> 1) & 1) ? SM_A1 : SM_A0) + (ch & 1) * 256;
        const uint32_t bbase = sb + ((ch & 1) ? SM_B1 : SM_B0);

        #pragma unroll
        for (int ks = 0; ks < 8; ++ks) {
            uint32_t ab = abase + (uint32_t)(wrow + (l >> 2)) * 528 + (uint32_t)(ks * 8 + (l & 3)) * 4;
            uint32_t A[2][4];
            #pragma unroll
            for (int mb = 0; mb < 2; ++mb) {
                uint32_t p = ab + mb * (16 * 528);
                A[mb][0] = cvt_tf32(lds32f(p));
                A[mb][1] = cvt_tf32(lds32f(p + 8 * 528));
                A[mb][2] = cvt_tf32(lds32f(p + 16));
                A[mb][3] = cvt_tf32(lds32f(p + 8 * 528 + 16));
            }
            #pragma unroll
            for (int bpi = 0; bpi < 4; ++bpi) {
                uint32_t q0, q1, q2, q3;
                lds128u(bbase + (uint32_t)(ks * 8 + nh * 4 + bpi) * 512 + (uint32_t)l * 16,
                        q0, q1, q2, q3);
                mma8(acc[0][2 * bpi],     A[0][0], A[0][1], A[0][2], A[0][3], q0, q1);
                mma8(acc[1][2 * bpi],     A[1][0], A[1][1], A[1][2], A[1][3], q0, q1);
                mma8(acc[0][2 * bpi + 1], A[0][0], A[0][1], A[0][2], A[0][3], q2, q3);
                mma8(acc[1][2 * bpi + 1], A[1][0], A[1][1], A[1][2], A[1][3], q2, q3);
            }
        }

        if (ch == 3 || ch == 5) {
            // epilogue -> smem (H1 to A0 after ch3, H2=relu to A1 after ch5)
            const uint32_t dst = sb + (ch == 3 ? SM_A0 : SM_A1);
            const uint32_t bo  = sb + SM_BIAS + (ch == 3 ? 0 : 512) + (uint32_t)nh * 256;
            const bool dorelu = (ch == 5);
            #pragma unroll
            for (int nb = 0; nb < 8; ++nb) {
                float bx, by;
                lds64f(bo + (uint32_t)(nb * 8 + (l & 3) * 2) * 4, bx, by);
                #pragma unroll
                for (int mb = 0; mb < 2; ++mb) {
                    float v0 = acc[mb][nb][0] + bx, v1 = acc[mb][nb][1] + by;
                    float v2 = acc[mb][nb][2] + bx, v3 = acc[mb][nb][3] + by;
                    if (dorelu) {
                        v0 = fmaxf(v0, 0.f); v1 = fmaxf(v1, 0.f);
                        v2 = fmaxf(v2, 0.f); v3 = fmaxf(v3, 0.f);
                    }
                    uint32_t sa = dst + (uint32_t)(wrow + mb * 16 + (l >> 2)) * 528
                                      + (uint32_t)(nh * 64 + nb * 8 + (l & 3) * 2) * 4;
                    sts64f(sa, v0, v1);
                    sts64f(sa + 8 * 528, v2, v3);
                    acc[mb][nb][0] = 0.f; acc[mb][nb][1] = 0.f;
                    acc[mb][nb][2] = 0.f; acc[mb][nb][3] = 0.f;
                }
            }
        } else if (ch == 7) {
            // final epilogue -> global Y, plus fused per-tile column sums
            const size_t rb = (size_t)t * 128 + wrow + (l >> 2);
            float cs[8][2];
            #pragma unroll
            for (int nb = 0; nb < 8; ++nb) { cs[nb][0] = 0.f; cs[nb][1] = 0.f; }
            #pragma unroll
            for (int nb = 0; nb < 8; ++nb) {
                float bx, by;
                lds64f(sb + SM_BIAS + 1024 + (uint32_t)(nh * 64 + nb * 8 + (l & 3) * 2) * 4, bx, by);
                #pragma unroll
                for (int mb = 0; mb < 2; ++mb) {
                    float v0 = acc[mb][nb][0] + bx, v1 = acc[mb][nb][1] + by;
                    float v2 = acc[mb][nb][2] + bx, v3 = acc[mb][nb][3] + by;
                    size_t r0 = (rb + mb * 16) * 128 + nh * 64 + nb * 8 + (l & 3) * 2;
                    *(float2*)(out + r0)            = make_float2(v0, v1);
                    *(float2*)(out + r0 + 8 * 128)  = make_float2(v2, v3);
                    cs[nb][0] += v0 + v2;
                    cs[nb][1] += v1 + v3;
                }
            }
            // reduce lanes with equal (l&3): offsets 16,8,4 -> lanes 0..3
            #pragma unroll
            for (int nb = 0; nb < 8; ++nb) {
                #pragma unroll
                for (int j = 0; j < 2; ++j) {
                    float s = cs[nb][j];
                    s += __shfl_down_sync(0xFFFFFFFFu, s, 16);
                    s += __shfl_down_sync(0xFFFFFFFFu, s, 8);
                    s += __shfl_down_sync(0xFFFFFFFFu, s, 4);
                    if (l < 4)
                        ((float*)(smem + SM_RED))[(w >> 1) * 128 + nh * 64 + nb * 8 + l * 2 + j] = s;
                }
            }
        }

        __syncthreads();

        if (ch + 2 < 8) {   // prefetch weight chunk ch+2 into buffer (ch&1)
            uint32_t bdst = sb + ((ch & 1) ? SM_B1 : SM_B0);
            const float* wsrc = g_wpack + (ch + 2) * 8192;
            for (int i = tid; i < 2048; i += 256) CP16(bdst + i * 16, wsrc + i * 4);
            CP_COMMIT();
        }
    }

    // fold 4 row-groups -> g_part[t][128]
    if (tid < 128) {
        const float* R = (const float*)(smem + SM_RED);
        g_part[(size_t)t * 128 + tid] = R[tid] + R[128 + tid] + R[256 + tid] + R[384 + tid];
    }
}

// ---------------- out = S - Y (in place, float4) ----------------
__global__ void subtract_kernel(float* __restrict__ out) {
    __shared__ float4 S4[32];
    int b = blockIdx.x, nc = blockIdx.y, tid = threadIdx.x;
    if (tid < 128) {
        float s = 0.f;
        const float* gp = g_part + (size_t)b * 32 * 128 + tid;
        #pragma unroll
        for (int c = 0; c < 32; ++c) s += gp[c * 128];
        ((float*)S4)[tid] = s;
    }
    __syncthreads();
    float4* p = (float4*)(out + ((size_t)b * 4096 + (size_t)nc * 128) * 128);
    for (int i = tid; i < 4096; i += 256) {
        float4 s = S4[i & 31];
        float4 v = p[i];
        p[i] = make_float4(s.x - v.x, s.y - v.y, s.z - v.z, s.w - v.w);
    }
}

// ---------------- launch ----------------
extern "C" void kernel_launch(void* const* d_in, const int* in_sizes, int n_in,
                              void* d_out, int out_size) {
    const float* X  = (const float*)d_in[0];
    const float* Wp = (const float*)d_in[1];
    const float* bp = (const float*)d_in[2];
    const float* W1 = (const float*)d_in[3];
    const float* b1 = (const float*)d_in[4];
    const float* W2 = (const float*)d_in[5];
    const float* b2 = (const float*)d_in[6];
    float* out = (float*)d_out;

    cudaFuncSetAttribute(fused_kernel,
                         cudaFuncAttributeMaxDynamicSharedMemorySize, SMEM_SZ);

    prep_kernel<<<256, 256>>>(Wp, W1, W2);
    fused_kernel<<<512, 256, SMEM_SZ>>>(X, bp, b1, b2, out);
    subtract_kernel<<<dim3(16, 32), 256>>>(out);
}

// round 5
// speedup vs baseline: 1.7546x; 1.3569x over previous
#include <cuda_runtime.h>
#include <cuda_fp16.h>
#include <cstdint>

// ============================================================================
// X[16,4096,256] -> proj(256->128)+bp -> relu(W1+b1) -> W2+b2 = Y
// out[b,n,:] = sum_m Y[b,m,:] - Y[b,n,:]
// mma.sync.m16n8k16 fp16 (f32 accum). 512 CTAs x 256 thr (8 warps):
// warp w -> rows (w>>1)*32..+32, n-half (w&1)*64..+64.
// Column sums fused into the final epilogue -> g_part[tile][128].
// ============================================================================

__device__ __align__(16) uint32_t g_wpack[8 * 4096];  // 8 chunks x 16KB fp16 packed
__device__ float g_part[512 * 128];

// ---------------- helpers ----------------
__device__ __forceinline__ uint32_t smem_u32(const void* p) {
    uint32_t a;
    asm("{ .reg .u64 t; cvta.to.shared.u64 t, %1; cvt.u32.u64 %0, t; }" : "=r"(a) : "l"(p));
    return a;
}
__device__ __forceinline__ void lds64f(uint32_t a, float& x, float& y) {
    asm volatile("ld.shared.v2.f32 {%0,%1}, [%2];" : "=f"(x), "=f"(y) : "r"(a));
}
__device__ __forceinline__ void lds128u(uint32_t a, uint32_t& x, uint32_t& y, uint32_t& z, uint32_t& w) {
    asm volatile("ld.shared.v4.b32 {%0,%1,%2,%3}, [%4];" : "=r"(x), "=r"(y), "=r"(z), "=r"(w) : "r"(a));
}
__device__ __forceinline__ void sts64f(uint32_t a, float x, float y) {
    asm volatile("st.shared.v2.f32 [%0], {%1,%2};" :: "r"(a), "f"(x), "f"(y));
}
// pack {lo, hi} floats -> f16x2 (lo in low half)
__device__ __forceinline__ uint32_t packh2(float lo, float hi) {
    uint32_t u;
    asm("cvt.rn.f16x2.f32 %0, %1, %2;" : "=r"(u) : "f"(hi), "f"(lo));
    return u;
}
__device__ __forceinline__ void mma16(float* d,
                                      uint32_t a0, uint32_t a1, uint32_t a2, uint32_t a3,
                                      uint32_t b0, uint32_t b1) {
    asm volatile(
        "mma.sync.aligned.m16n8k16.row.col.f32.f16.f16.f32 "
        "{%0,%1,%2,%3}, {%4,%5,%6,%7}, {%8,%9}, {%0,%1,%2,%3};"
        : "+f"(d[0]), "+f"(d[1]), "+f"(d[2]), "+f"(d[3])
        : "r"(a0), "r"(a1), "r"(a2), "r"(a3), "r"(b0), "r"(b1));
}
#define CP16(dst, src)  asm volatile("cp.async.cg.shared.global [%0], [%1], 16;" :: "r"(dst), "l"(src))
#define CP_COMMIT()     asm volatile("cp.async.commit_group;" ::: "memory")
#define CP_WAIT(n)      asm volatile("cp.async.wait_group %0;" :: "n"(n) : "memory")

// ============================================================================
// prep: pack weights (fp16) into lane-ordered quad layout.
// chunk c (0..7) = 16KB K-slice of 64 rows x 128 cols (0-3:Wp, 4-5:W1, 6-7:W2).
// uint32 idx within chunk: ((ks*8+bp)*32 + lane)*4 + q, where
//   k_local = ks*16 + (q&1)*8 + (lane&3)*2  (pair k, k+1 packed)
//   n       = bp*16 + (q>>1)*8 + (lane>>2)
// One LDS.128 per (ks,bp,lane) = B-frags {b0,b1} for n-blocks 2bp, 2bp+1.
// ============================================================================
__global__ void prep_kernel(const float* __restrict__ Wp,
                            const float* __restrict__ W1,
                            const float* __restrict__ W2) {
    int i = blockIdx.x * 256 + threadIdx.x;          // 32768 total
    int chunk = i >> 12;
    int within = i & 4095;
    int q = within & 3, ln = (within >> 2) & 31, bpks = within >> 7;
    int bpi = bpks & 7, ks = bpks >> 3;
    int kl = ks * 16 + (q & 1) * 8 + (ln & 3) * 2;
    int n = bpi * 16 + (q >> 1) * 8 + (ln >> 2);
    const float* W;
    int krow;
    if (chunk < 4)      { W = Wp; krow = chunk * 64 + kl; }
    else if (chunk < 6) { W = W1; krow = (chunk - 4) * 64 + kl; }
    else                { W = W2; krow = (chunk - 6) * 64 + kl; }
    float w0 = W[(size_t)krow * 128 + n];
    float w1 = W[(size_t)(krow + 1) * 128 + n];
    g_wpack[i] = packh2(w0, w1);
}

// ============================================================================
// fused kernel. A stride = 136 floats (544B): conflict-free LDS.64 / STS.64.
// ============================================================================
#define SM_A0   0
#define SM_A1   69632                 // 128*544
#define SM_B0   139264
#define SM_B1   155648
#define SM_BIAS 172032                // bp[128], b1[128], b2[128]
#define SM_RED  173568                // 4*128 floats
#define SMEM_SZ 175616

__global__ void __launch_bounds__(256, 1) fused_kernel(
    const float* __restrict__ X,
    const float* __restrict__ bp,
    const float* __restrict__ b1,
    const float* __restrict__ b2,
    float* __restrict__ out)
{
    extern __shared__ char smem[];
    const uint32_t sb = smem_u32(smem);
    const int tid = threadIdx.x;
    const int l = tid & 31;
    const int w = tid >> 5;
    const int wrow = (w >> 1) * 32;        // row group
    const int nh = w & 1;                  // n-half (0: cols 0-63, 1: 64-127)
    const int t = blockIdx.x;

    if (tid < 128) {
        ((float*)(smem + SM_BIAS))[tid]       = bp[tid];
        ((float*)(smem + SM_BIAS))[128 + tid] = b1[tid];
        ((float*)(smem + SM_BIAS))[256 + tid] = b2[tid];
    }

    // prologue: group0 = Xh0->A0 + W0->B0 ; group1 = Xh1->A1 + W1->B1
    const float* xbase = X + (size_t)t * 128 * 256;
    #pragma unroll
    for (int h = 0; h < 2; ++h) {
        uint32_t adst = sb + (h ? SM_A1 : SM_A0);
        for (int i = tid; i < 4096; i += 256) {
            int r = i >> 5, c16 = i & 31;
            CP16(adst + r * 544 + c16 * 16,
                 xbase + (size_t)r * 256 + h * 128 + c16 * 4);
        }
        uint32_t bdst = sb + (h ? SM_B1 : SM_B0);
        const uint4* wsrc = (const uint4*)(g_wpack + h * 4096);
        for (int i = tid; i < 1024; i += 256) CP16(bdst + i * 16, wsrc + i);
        CP_COMMIT();
    }

    float acc[2][8][4];
    #pragma unroll
    for (int m = 0; m < 2; ++m)
        #pragma unroll
        for (int nb = 0; nb < 8; ++nb)
            #pragma unroll
            for (int k = 0; k < 4; ++k) acc[m][nb][k] = 0.f;

    for (int ch = 0; ch < 8; ++ch) {
        if (ch < 7) { CP_WAIT(1); } else { CP_WAIT(0); }
        __syncthreads();

        // chunks 0,1 read A0 (Xh0); 2,3 A1 (Xh1); 4,5 A0 (H1); 6,7 A1 (H2)
        const uint32_t abase = sb + (((ch >> 1) & 1) ? SM_A1 : SM_A0) + (ch & 1) * 256;
        const uint32_t bbase = sb + ((ch & 1) ? SM_B1 : SM_B0);

        #pragma unroll
        for (int ks = 0; ks < 4; ++ks) {
            uint32_t ab = abase + (uint32_t)(wrow + (l >> 2)) * 544
                                + (uint32_t)(ks * 16 + (l & 3) * 2) * 4;
            uint32_t A[2][4];
            #pragma unroll
            for (int mb = 0; mb < 2; ++mb) {
                uint32_t p = ab + mb * (16 * 544);
                float x0, x1, y0, y1, z0, z1, u0, u1;
                lds64f(p, x0, x1);                  // row,   k0..k0+1
                lds64f(p + 8 * 544, y0, y1);        // row+8, k0..k0+1
                lds64f(p + 32, z0, z1);             // row,   k0+8..+9
                lds64f(p + 8 * 544 + 32, u0, u1);   // row+8, k0+8..+9
                A[mb][0] = packh2(x0, x1);
                A[mb][1] = packh2(y0, y1);
                A[mb][2] = packh2(z0, z1);
                A[mb][3] = packh2(u0, u1);
            }
            #pragma unroll
            for (int bpi = 0; bpi < 4; ++bpi) {
                uint32_t q0, q1, q2, q3;
                lds128u(bbase + (uint32_t)(ks * 8 + nh * 4 + bpi) * 512 + (uint32_t)l * 16,
                        q0, q1, q2, q3);
                mma16(acc[0][2 * bpi],     A[0][0], A[0][1], A[0][2], A[0][3], q0, q1);
                mma16(acc[1][2 * bpi],     A[1][0], A[1][1], A[1][2], A[1][3], q0, q1);
                mma16(acc[0][2 * bpi + 1], A[0][0], A[0][1], A[0][2], A[0][3], q2, q3);
                mma16(acc[1][2 * bpi + 1], A[1][0], A[1][1], A[1][2], A[1][3], q2, q3);
            }
        }

        if (ch == 3 || ch == 5) {
            // epilogue -> smem (H1 to A0 after ch3, H2=relu to A1 after ch5)
            const uint32_t dst = sb + (ch == 3 ? SM_A0 : SM_A1);
            const uint32_t bo  = sb + SM_BIAS + (ch == 3 ? 0 : 512) + (uint32_t)nh * 256;
            const bool dorelu = (ch == 5);
            #pragma unroll
            for (int nb = 0; nb < 8; ++nb) {
                float bx, by;
                lds64f(bo + (uint32_t)(nb * 8 + (l & 3) * 2) * 4, bx, by);
                #pragma unroll
                for (int mb = 0; mb < 2; ++mb) {
                    float v0 = acc[mb][nb][0] + bx, v1 = acc[mb][nb][1] + by;
                    float v2 = acc[mb][nb][2] + bx, v3 = acc[mb][nb][3] + by;
                    if (dorelu) {
                        v0 = fmaxf(v0, 0.f); v1 = fmaxf(v1, 0.f);
                        v2 = fmaxf(v2, 0.f); v3 = fmaxf(v3, 0.f);
                    }
                    uint32_t sa = dst + (uint32_t)(wrow + mb * 16 + (l >> 2)) * 544
                                      + (uint32_t)(nh * 64 + nb * 8 + (l & 3) * 2) * 4;
                    sts64f(sa, v0, v1);
                    sts64f(sa + 8 * 544, v2, v3);
                    acc[mb][nb][0] = 0.f; acc[mb][nb][1] = 0.f;
                    acc[mb][nb][2] = 0.f; acc[mb][nb][3] = 0.f;
                }
            }
        } else if (ch == 7) {
            // final epilogue -> global Y, plus fused per-tile column sums
            const size_t rb = (size_t)t * 128 + wrow + (l >> 2);
            float cs[8][2];
            #pragma unroll
            for (int nb = 0; nb < 8; ++nb) { cs[nb][0] = 0.f; cs[nb][1] = 0.f; }
            #pragma unroll
            for (int nb = 0; nb < 8; ++nb) {
                float bx, by;
                lds64f(sb + SM_BIAS + 1024 + (uint32_t)(nh * 64 + nb * 8 + (l & 3) * 2) * 4, bx, by);
                #pragma unroll
                for (int mb = 0; mb < 2; ++mb) {
                    float v0 = acc[mb][nb][0] + bx, v1 = acc[mb][nb][1] + by;
                    float v2 = acc[mb][nb][2] + bx, v3 = acc[mb][nb][3] + by;
                    size_t r0 = (rb + mb * 16) * 128 + nh * 64 + nb * 8 + (l & 3) * 2;
                    *(float2*)(out + r0)            = make_float2(v0, v1);
                    *(float2*)(out + r0 + 8 * 128)  = make_float2(v2, v3);
                    cs[nb][0] += v0 + v2;
                    cs[nb][1] += v1 + v3;
                }
            }
            #pragma unroll
            for (int nb = 0; nb < 8; ++nb) {
                #pragma unroll
                for (int j = 0; j < 2; ++j) {
                    float s = cs[nb][j];
                    s += __shfl_down_sync(0xFFFFFFFFu, s, 16);
                    s += __shfl_down_sync(0xFFFFFFFFu, s, 8);
                    s += __shfl_down_sync(0xFFFFFFFFu, s, 4);
                    if (l < 4)
                        ((float*)(smem + SM_RED))[(w >> 1) * 128 + nh * 64 + nb * 8 + l * 2 + j] = s;
                }
            }
        }

        __syncthreads();

        if (ch + 2 < 8) {   // prefetch weight chunk ch+2 into buffer (ch&1)
            uint32_t bdst = sb + ((ch & 1) ? SM_B1 : SM_B0);
            const uint4* wsrc = (const uint4*)(g_wpack + (ch + 2) * 4096);
            for (int i = tid; i < 1024; i += 256) CP16(bdst + i * 16, wsrc + i);
            CP_COMMIT();
        }
    }

    // fold 4 row-groups -> g_part[t][128]
    if (tid < 128) {
        const float* R = (const float*)(smem + SM_RED);
        g_part[(size_t)t * 128 + tid] = R[tid] + R[128 + tid] + R[256 + tid] + R[384 + tid];
    }
}

// ---------------- out = S - Y (in place, float4) ----------------
__global__ void subtract_kernel(float* __restrict__ out) {
    __shared__ float4 S4[32];
    int b = blockIdx.x, nc = blockIdx.y, tid = threadIdx.x;
    if (tid < 128) {
        float s = 0.f;
        const float* gp = g_part + (size_t)b * 32 * 128 + tid;
        #pragma unroll
        for (int c = 0; c < 32; ++c) s += gp[c * 128];
        ((float*)S4)[tid] = s;
    }
    __syncthreads();
    float4* p = (float4*)(out + ((size_t)b * 4096 + (size_t)nc * 128) * 128);
    for (int i = tid; i < 4096; i += 256) {
        float4 s = S4[i & 31];
        float4 v = p[i];
        p[i] = make_float4(s.x - v.x, s.y - v.y, s.z - v.z, s.w - v.w);
    }
}

// ---------------- launch ----------------
extern "C" void kernel_launch(void* const* d_in, const int* in_sizes, int n_in,
                              void* d_out, int out_size) {
    const float* X  = (const float*)d_in[0];
    const float* Wp = (const float*)d_in[1];
    const float* bp = (const float*)d_in[2];
    const float* W1 = (const float*)d_in[3];
    const float* b1 = (const float*)d_in[4];
    const float* W2 = (const float*)d_in[5];
    const float* b2 = (const float*)d_in[6];
    float* out = (float*)d_out;

    cudaFuncSetAttribute(fused_kernel,
                         cudaFuncAttributeMaxDynamicSharedMemorySize, SMEM_SZ);

    prep_kernel<<<128, 256>>>(Wp, W1, W2);
    fused_kernel<<<512, 256, SMEM_SZ>>>(X, bp, b1, b2, out);
    subtract_kernel<<<dim3(16, 32), 256>>>(out);
}